// round 1
// baseline (speedup 1.0000x reference)
#include <cuda_runtime.h>
#include <math.h>

// Problem dims
#define B_DIM  1024
#define H_DIM  1024
#define G_DIM  4096   // 4*H
#define IN_DIM 1024
#define C_DIM  1000

// GEMM tiling
#define BM 64
#define BN 64
#define BK 16
#define TM 4
#define TN 4
#define THREADS 256
#define SPAD 4

// Scratch for hidden_vec = sigmoid(gi*xi + gs*hs), [B, 4H]
__device__ float g_hidden[B_DIM * G_DIM];

// Load a [BM rows x BK cols] tile of a row-major [rows, ld] matrix into
// smem transposed as dst[k][m]. Guarded on k < kmax (C_DIM=1000 tail).
__device__ __forceinline__ void load_tile(const float* __restrict__ src, int ld,
                                          int row0, int k0, int kmax,
                                          float dst[BK][BM + SPAD], int tid) {
#pragma unroll
    for (int r = 0; r < (BM * BK) / THREADS; r++) {
        int idx = tid + r * THREADS;   // 0..1023
        int kk  = idx & (BK - 1);
        int m   = idx / BK;
        int k   = k0 + kk;
        dst[kk][m] = (k < kmax) ? src[(row0 + m) * ld + k] : 0.0f;
    }
}

__global__ __launch_bounds__(THREADS) void fused_gates_kernel(
    const float* __restrict__ core_input,   // [B, IN]
    const float* __restrict__ h_state,      // [B, H]
    const float* __restrict__ concept,      // [B, C]
    const float* __restrict__ W_in,         // [4H, IN]
    const float* __restrict__ W_st,         // [4H, H]
    const float* __restrict__ W_ci,         // [4H, C]
    const float* __restrict__ W_cs)         // [4H, C]
{
    __shared__ float sA [BK][BM + SPAD];
    __shared__ float sB0[BK][BN + SPAD];
    __shared__ float sB1[BK][BN + SPAD];

    const int tid   = threadIdx.x;
    const int tx    = tid & 15;        // 16 cols of threads
    const int ty    = tid >> 4;        // 16 rows of threads
    const int brow0 = blockIdx.y * BM; // batch tile
    const int gcol0 = blockIdx.x * BN; // gate-column tile

    float acc_xi[TM][TN] = {};
    float acc_hs[TM][TN] = {};
    float acc_gi[TM][TN] = {};
    float acc_gs[TM][TN] = {};

    // ---------- Phase 1: xi = core_input @ W_in^T ----------
    for (int k0 = 0; k0 < IN_DIM; k0 += BK) {
        load_tile(core_input, IN_DIM, brow0, k0, IN_DIM, sA,  tid);
        load_tile(W_in,       IN_DIM, gcol0, k0, IN_DIM, sB0, tid);
        __syncthreads();
#pragma unroll
        for (int kk = 0; kk < BK; kk++) {
            float a[TM], b[TN];
#pragma unroll
            for (int i = 0; i < TM; i++) a[i] = sA[kk][ty * TM + i];
#pragma unroll
            for (int j = 0; j < TN; j++) b[j] = sB0[kk][tx * TN + j];
#pragma unroll
            for (int i = 0; i < TM; i++)
#pragma unroll
                for (int j = 0; j < TN; j++) acc_xi[i][j] += a[i] * b[j];
        }
        __syncthreads();
    }

    // ---------- Phase 2: hs = h_state @ W_st^T ----------
    for (int k0 = 0; k0 < H_DIM; k0 += BK) {
        load_tile(h_state, H_DIM, brow0, k0, H_DIM, sA,  tid);
        load_tile(W_st,    H_DIM, gcol0, k0, H_DIM, sB0, tid);
        __syncthreads();
#pragma unroll
        for (int kk = 0; kk < BK; kk++) {
            float a[TM], b[TN];
#pragma unroll
            for (int i = 0; i < TM; i++) a[i] = sA[kk][ty * TM + i];
#pragma unroll
            for (int j = 0; j < TN; j++) b[j] = sB0[kk][tx * TN + j];
#pragma unroll
            for (int i = 0; i < TM; i++)
#pragma unroll
                for (int j = 0; j < TN; j++) acc_hs[i][j] += a[i] * b[j];
        }
        __syncthreads();
    }

    // ---------- Phase 3: gi = concept @ W_ci^T, gs = concept @ W_cs^T ----------
    for (int k0 = 0; k0 < C_DIM; k0 += BK) {
        load_tile(concept, C_DIM, brow0, k0, C_DIM, sA,  tid);
        load_tile(W_ci,    C_DIM, gcol0, k0, C_DIM, sB0, tid);
        load_tile(W_cs,    C_DIM, gcol0, k0, C_DIM, sB1, tid);
        __syncthreads();
#pragma unroll
        for (int kk = 0; kk < BK; kk++) {
            float a[TM], b0[TN], b1[TN];
#pragma unroll
            for (int i = 0; i < TM; i++) a[i] = sA[kk][ty * TM + i];
#pragma unroll
            for (int j = 0; j < TN; j++) { b0[j] = sB0[kk][tx * TN + j]; b1[j] = sB1[kk][tx * TN + j]; }
#pragma unroll
            for (int i = 0; i < TM; i++)
#pragma unroll
                for (int j = 0; j < TN; j++) {
                    acc_gi[i][j] += a[i] * b0[j];
                    acc_gs[i][j] += a[i] * b1[j];
                }
        }
        __syncthreads();
    }

    // ---------- Epilogue: hidden = sigmoid(gi*xi + gs*hs) ----------
#pragma unroll
    for (int i = 0; i < TM; i++) {
        int row = brow0 + ty * TM + i;
#pragma unroll
        for (int j = 0; j < TN; j++) {
            int col = gcol0 + tx * TN + j;
            float z = acc_gi[i][j] * acc_xi[i][j] + acc_gs[i][j] * acc_hs[i][j];
            float s = 1.0f / (1.0f + expf(-z));
            g_hidden[row * G_DIM + col] = s;
        }
    }
}

// LSTM cell epilogue: split gates along columns, compute c_t and h_t.
__global__ __launch_bounds__(256) void lstm_epilogue_kernel(
    const float* __restrict__ c_state,  // [B, H]
    float* __restrict__ out)            // [h_t | c_t], each B*H
{
    int idx = blockIdx.x * blockDim.x + threadIdx.x;  // 0 .. B*H-1
    if (idx >= B_DIM * H_DIM) return;
    int b = idx >> 10;       // /H_DIM
    int h = idx & 1023;      // %H_DIM
    const float* row = g_hidden + b * G_DIM;
    float i_t = row[h];
    float f_t = row[H_DIM + h];
    float o_t = row[2 * H_DIM + h];
    float c_c = row[3 * H_DIM + h];
    float c_t = i_t * c_c + f_t * c_state[idx];
    out[idx]                 = o_t * tanhf(c_t);  // h_t
    out[B_DIM * H_DIM + idx] = c_t;               // c_t
}

extern "C" void kernel_launch(void* const* d_in, const int* in_sizes, int n_in,
                              void* d_out, int out_size) {
    const float* core_input = (const float*)d_in[0];
    const float* h_state    = (const float*)d_in[1];
    const float* c_state    = (const float*)d_in[2];
    const float* concept    = (const float*)d_in[3];
    const float* W_in       = (const float*)d_in[4];
    const float* W_st       = (const float*)d_in[5];
    const float* W_ci       = (const float*)d_in[6];
    const float* W_cs       = (const float*)d_in[7];
    float* out = (float*)d_out;

    dim3 grid(G_DIM / BN, B_DIM / BM);   // (64, 16)
    fused_gates_kernel<<<grid, THREADS>>>(core_input, h_state, concept,
                                          W_in, W_st, W_ci, W_cs);

    int n = B_DIM * H_DIM;
    lstm_epilogue_kernel<<<(n + 255) / 256, 256>>>(c_state, out);
}

// round 4
// speedup vs baseline: 2.5743x; 2.5743x over previous
#include <cuda_runtime.h>
#include <cstdint>
#include <math.h>

#define B_DIM  1024
#define H_DIM  1024
#define IN_DIM 1024
#define C_DIM  1000

#define KC 32            // K chunk
#define ASTRIDE 137      // [k][m] smem stride, 137 % 32 == 9 (STS conflict-free, LDS <=2-way)
#define BSTRIDE 73       // [k][n] smem stride, 73 % 32 == 9

// smem float offsets (double buffered A, B0, B1)
#define A_OFF(b)  ((b) * (KC * ASTRIDE))
#define B0_OFF(b) (2 * KC * ASTRIDE + (b) * (KC * BSTRIDE))
#define B1_OFF(b) (2 * KC * ASTRIDE + 2 * KC * BSTRIDE + (b) * (KC * BSTRIDE))
#define SMEM_FLOATS (2 * KC * ASTRIDE + 4 * KC * BSTRIDE)   // 18112 floats = 72448 B
#define HID_STRIDE 65

__device__ __forceinline__ uint32_t tf32r(float x) {
    uint32_t r;
    asm("cvt.rna.tf32.f32 %0, %1;" : "=r"(r) : "f"(x));
    return r;
}

__device__ __forceinline__ void mma8(float* d, const uint32_t* a, const uint32_t* b) {
    asm volatile(
        "mma.sync.aligned.m16n8k8.row.col.f32.tf32.tf32.f32 "
        "{%0,%1,%2,%3}, {%4,%5,%6,%7}, {%8,%9}, {%0,%1,%2,%3};"
        : "+f"(d[0]), "+f"(d[1]), "+f"(d[2]), "+f"(d[3])
        : "r"(a[0]), "r"(a[1]), "r"(a[2]), "r"(a[3]), "r"(b[0]), "r"(b[1]));
}

// One K=32 chunk, single B operand. Warp tile 64(M) x 16(N): mt 0..3, nt 0..1.
__device__ __forceinline__ void compute_chunk(const uint32_t* As, const uint32_t* Bs,
                                              float (&acc)[32],
                                              int wm, int wn, int gid, int ctid) {
#pragma unroll
    for (int ks = 0; ks < 4; ks++) {
        uint32_t bf[2][2];
#pragma unroll
        for (int nt = 0; nt < 2; nt++) {
            int n = wn * 16 + nt * 8 + gid;
            bf[nt][0] = Bs[(ks * 8 + ctid) * BSTRIDE + n];
            bf[nt][1] = Bs[(ks * 8 + ctid + 4) * BSTRIDE + n];
        }
#pragma unroll
        for (int mt = 0; mt < 4; mt++) {
            int m = wm * 64 + mt * 16 + gid;
            uint32_t af[4];
            af[0] = As[(ks * 8 + ctid) * ASTRIDE + m];
            af[1] = As[(ks * 8 + ctid) * ASTRIDE + m + 8];
            af[2] = As[(ks * 8 + ctid + 4) * ASTRIDE + m];
            af[3] = As[(ks * 8 + ctid + 4) * ASTRIDE + m + 8];
#pragma unroll
            for (int nt = 0; nt < 2; nt++)
                mma8(&acc[mt * 8 + nt * 4], af, bf[nt]);
        }
    }
}

// Dual-B chunk (concept phase): shared A fragments, two accumulator sets.
__device__ __forceinline__ void compute_chunk2(const uint32_t* As, const uint32_t* B0s,
                                               const uint32_t* B1s,
                                               float (&acc0)[32], float (&acc1)[32],
                                               int wm, int wn, int gid, int ctid) {
#pragma unroll
    for (int ks = 0; ks < 4; ks++) {
        uint32_t bf0[2][2], bf1[2][2];
#pragma unroll
        for (int nt = 0; nt < 2; nt++) {
            int n = wn * 16 + nt * 8 + gid;
            bf0[nt][0] = B0s[(ks * 8 + ctid) * BSTRIDE + n];
            bf0[nt][1] = B0s[(ks * 8 + ctid + 4) * BSTRIDE + n];
            bf1[nt][0] = B1s[(ks * 8 + ctid) * BSTRIDE + n];
            bf1[nt][1] = B1s[(ks * 8 + ctid + 4) * BSTRIDE + n];
        }
#pragma unroll
        for (int mt = 0; mt < 4; mt++) {
            int m = wm * 64 + mt * 16 + gid;
            uint32_t af[4];
            af[0] = As[(ks * 8 + ctid) * ASTRIDE + m];
            af[1] = As[(ks * 8 + ctid) * ASTRIDE + m + 8];
            af[2] = As[(ks * 8 + ctid + 4) * ASTRIDE + m];
            af[3] = As[(ks * 8 + ctid + 4) * ASTRIDE + m + 8];
#pragma unroll
            for (int nt = 0; nt < 2; nt++) {
                mma8(&acc0[mt * 8 + nt * 4], af, bf0[nt]);
                mma8(&acc1[mt * 8 + nt * 4], af, bf1[nt]);
            }
        }
    }
}

// LDG one chunk into registers. lrow = tid>>3 (row within 32-row group), lkg = tid&7.
__device__ __forceinline__ void ldg_chunk(
    int g, int brow0, int hcol0,
    const float* __restrict__ ci, const float* __restrict__ hsin,
    const float* __restrict__ cc, const float* __restrict__ Wi,
    const float* __restrict__ Ws, const float* __restrict__ Wci,
    const float* __restrict__ Wcs,
    int lrow, int lkg, float4 (&ra)[4], float4 (&rb0)[2], float4 (&rb1)[2]) {
    int ph = g >> 5, k0 = (g & 31) * KC;
    const float *A, *B0, *B1 = nullptr;
    int ld, kmax;
    if (ph == 0)      { A = ci;   B0 = Wi;  ld = IN_DIM; kmax = IN_DIM; }
    else if (ph == 1) { A = hsin; B0 = Ws;  ld = H_DIM;  kmax = H_DIM; }
    else              { A = cc;   B0 = Wci; B1 = Wcs; ld = C_DIM; kmax = C_DIM; }
    int kf = k0 + lkg * 4;
    bool ok = kf < kmax;          // C_DIM % 4 == 0 so float4 guard is exact
    const float4 z4 = make_float4(0.f, 0.f, 0.f, 0.f);
#pragma unroll
    for (int p = 0; p < 4; p++) {
        int m = p * 32 + lrow;
        ra[p] = ok ? *(const float4*)&A[(size_t)(brow0 + m) * ld + kf] : z4;
    }
#pragma unroll
    for (int p = 0; p < 2; p++) {
        int n = p * 32 + lrow;
        int rg = ((n >> 4) << 10) + hcol0 + (n & 15);   // gate row = sec*1024 + hcol
        rb0[p] = ok ? *(const float4*)&B0[(size_t)rg * ld + kf] : z4;
        if (B1) rb1[p] = ok ? *(const float4*)&B1[(size_t)rg * ld + kf] : z4;
    }
}

__device__ __forceinline__ void sts_chunk(uint32_t* As, uint32_t* B0s, uint32_t* B1s,
                                          bool dual, int lrow, int lkg,
                                          const float4 (&ra)[4], const float4 (&rb0)[2],
                                          const float4 (&rb1)[2]) {
#pragma unroll
    for (int p = 0; p < 4; p++) {
        const float* v = (const float*)&ra[p];
#pragma unroll
        for (int j = 0; j < 4; j++)
            As[(lkg * 4 + j) * ASTRIDE + p * 32 + lrow] = tf32r(v[j]);
    }
#pragma unroll
    for (int p = 0; p < 2; p++) {
        const float* v0 = (const float*)&rb0[p];
        const float* v1 = (const float*)&rb1[p];
#pragma unroll
        for (int j = 0; j < 4; j++) {
            B0s[(lkg * 4 + j) * BSTRIDE + p * 32 + lrow] = tf32r(v0[j]);
            if (dual) B1s[(lkg * 4 + j) * BSTRIDE + p * 32 + lrow] = tf32r(v1[j]);
        }
    }
}

__global__ void __launch_bounds__(256, 1) scn_mma_kernel(
    const float* __restrict__ core_input, const float* __restrict__ h_state,
    const float* __restrict__ c_state, const float* __restrict__ concept,
    const float* __restrict__ W_in, const float* __restrict__ W_st,
    const float* __restrict__ W_ci, const float* __restrict__ W_cs,
    float* __restrict__ out) {
    extern __shared__ uint32_t smf[];
    const int tid = threadIdx.x, lane = tid & 31, wid = tid >> 5;
    const int gid = lane >> 2, ctid = lane & 3;
    const int wm = wid >> 2, wn = wid & 3;           // warp grid 2(M) x 4(N)
    const int lrow = tid >> 3, lkg = tid & 7;
    const int hcol0 = blockIdx.x * 16;
    const int brow0 = blockIdx.y * 128;

    float axi[32] = {}, ahs[32] = {}, agi[32] = {}, ags[32] = {};
    float4 ra[4], rb0[2], rb1[2];

    ldg_chunk(0, brow0, hcol0, core_input, h_state, concept,
              W_in, W_st, W_ci, W_cs, lrow, lkg, ra, rb0, rb1);

    for (int g = 0; g < 96; g++) {
        const int buf = g & 1;
        const int ph = g >> 5;
        sts_chunk(smf + A_OFF(buf), smf + B0_OFF(buf), smf + B1_OFF(buf),
                  ph == 2, lrow, lkg, ra, rb0, rb1);
        __syncthreads();
        if (g + 1 < 96)
            ldg_chunk(g + 1, brow0, hcol0, core_input, h_state, concept,
                      W_in, W_st, W_ci, W_cs, lrow, lkg, ra, rb0, rb1);
        if (ph == 0)
            compute_chunk(smf + A_OFF(buf), smf + B0_OFF(buf), axi, wm, wn, gid, ctid);
        else if (ph == 1)
            compute_chunk(smf + A_OFF(buf), smf + B0_OFF(buf), ahs, wm, wn, gid, ctid);
        else
            compute_chunk2(smf + A_OFF(buf), smf + B0_OFF(buf), smf + B1_OFF(buf),
                           agi, ags, wm, wn, gid, ctid);
        // single barrier per iteration is safe with double buffering:
        // STS(g+2,buf) only happens after sync(g+1), which requires all threads
        // to have finished compute(g,buf).
    }
    __syncthreads();

    // ---- fused epilogue: hidden = sigmoid(gi*xi + gs*hs) staged in smem ----
    float* hid = (float*)smf;   // reuse: 128 x 65 floats
#pragma unroll
    for (int mt = 0; mt < 4; mt++)
#pragma unroll
        for (int nt = 0; nt < 2; nt++)
#pragma unroll
            for (int c = 0; c < 4; c++) {
                int i = mt * 8 + nt * 4 + c;
                int m = wm * 64 + mt * 16 + gid + ((c >> 1) ? 8 : 0);
                int n = wn * 16 + nt * 8 + ctid * 2 + (c & 1);
                float z = agi[i] * axi[i] + ags[i] * ahs[i];
                hid[m * HID_STRIDE + n] = 1.0f / (1.0f + expf(-z));
            }
    __syncthreads();

    // LSTM combine: n = sec*16 + j, secs = i, f, o, c_cand
    {
        int m = tid >> 1;
        int j0 = (tid & 1) * 8;
        const float* row = hid + m * HID_STRIDE;
        size_t gbase = (size_t)(brow0 + m) * H_DIM + hcol0 + j0;
#pragma unroll
        for (int i = 0; i < 8; i++) {
            int j = j0 + i;
            float it = row[j];
            float ft = row[16 + j];
            float ot = row[32 + j];
            float cc = row[48 + j];
            float cs = c_state[gbase + i];
            float ct = it * cc + ft * cs;
            float ht = ot * tanhf(ct);
            out[gbase + i] = ht;
            out[(size_t)B_DIM * H_DIM + gbase + i] = ct;
        }
    }
}

extern "C" void kernel_launch(void* const* d_in, const int* in_sizes, int n_in,
                              void* d_out, int out_size) {
    const float* core_input = (const float*)d_in[0];
    const float* h_state    = (const float*)d_in[1];
    const float* c_state    = (const float*)d_in[2];
    const float* concept    = (const float*)d_in[3];
    const float* W_in       = (const float*)d_in[4];
    const float* W_st       = (const float*)d_in[5];
    const float* W_ci       = (const float*)d_in[6];
    const float* W_cs       = (const float*)d_in[7];
    float* out = (float*)d_out;

    static bool configured = false;
    if (!configured) {
        cudaFuncSetAttribute(scn_mma_kernel,
                             cudaFuncAttributeMaxDynamicSharedMemorySize,
                             SMEM_FLOATS * 4);
        configured = true;
    }

    dim3 grid(64, 8);   // 64 h-col tiles x 8 batch tiles
    scn_mma_kernel<<<grid, 256, SMEM_FLOATS * 4>>>(
        core_input, h_state, c_state, concept, W_in, W_st, W_ci, W_cs, out);
}